// round 3
// baseline (speedup 1.0000x reference)
#include <cuda_runtime.h>
#include <math.h>

// Problem constants (fixed by setup_inputs)
#define TT   12
#define NF   32
#define NH   64
#define NG   256   // 4H
#define NO   8
#define MAXN 20000
#define MAXE 400000

// ---------------- device scratch (static, no allocation) ----------------
__device__ int   g_cnt [MAXN];
__device__ int   g_offs[MAXN + 1];
__device__ int   g_cur [MAXN];
__device__ int   g_esrc[MAXE];
__device__ float g_eew [MAXE];
__device__ float g_aggx[(size_t)TT * MAXN * NF];  // normalized wmean(x)  [T,N,F]
__device__ float g_xr  [(size_t)TT * MAXN * NH];  // relu(emb)            [T,N,H]
__device__ float g_axr [(size_t)TT * MAXN * NH];  // normalized wmean(xr) [T,N,H]
__device__ float g_aggh[(size_t)MAXN * NH];       // normalized wmean(h)  [N,H]
__device__ float g_h   [(size_t)MAXN * NH];
__device__ float g_c   [(size_t)MAXN * NH];
__device__ float g_h2  [(size_t)4 * MAXN * NH];   // h2 at t=8..11

// ---------------- CSR build ----------------
__global__ void k_zero_cnt(int N) {
    int i = blockIdx.x * blockDim.x + threadIdx.x;
    if (i < N) g_cnt[i] = 0;
}

__global__ void k_count(const int* __restrict__ dstv, int E) {
    int e = blockIdx.x * blockDim.x + threadIdx.x;
    if (e < E) atomicAdd(&g_cnt[dstv[e]], 1);
}

// single-block exclusive scan over counts -> offsets (+ cursor copy)
__global__ void k_scan(int N) {
    __shared__ int sh[1024];
    int tx = threadIdx.x;
    int total = 0;
    for (int base = 0; base < N; base += 1024) {
        int i = base + tx;
        int v = (i < N) ? g_cnt[i] : 0;
        sh[tx] = v;
        __syncthreads();
        for (int d = 1; d < 1024; d <<= 1) {
            int t = (tx >= d) ? sh[tx - d] : 0;
            __syncthreads();
            sh[tx] += t;
            __syncthreads();
        }
        if (i < N) {
            int ex = total + sh[tx] - v;
            g_offs[i] = ex;
            g_cur[i]  = ex;
        }
        total += sh[1023];
        __syncthreads();
    }
    if (tx == 0) g_offs[N] = total;
}

__global__ void k_scatter(const int* __restrict__ srcv, const int* __restrict__ dstv,
                          const float* __restrict__ ew, int E) {
    int e = blockIdx.x * blockDim.x + threadIdx.x;
    if (e >= E) return;
    int d = dstv[e];
    int p = atomicAdd(&g_cur[d], 1);
    g_esrc[p] = srcv[e];
    g_eew[p]  = ew[e];
}

// ---------------- generic gather aggregation (normalized) ----------------
// mode 0: in = x(param)  out = g_aggx   (C4 = NF/4, B = TT)
// mode 1: in = g_xr      out = g_axr    (C4 = NH/4, B = TT)
// mode 2: in = g_h       out = g_aggh   (C4 = NH/4, B = 1)
__global__ void k_aggregate(const float* __restrict__ in_ext, int mode, int N, int C4, int B) {
    const float* in;
    float* out;
    if (mode == 0)      { in = in_ext; out = g_aggx; }
    else if (mode == 1) { in = g_xr;   out = g_axr;  }
    else                { in = g_h;    out = g_aggh; }

    int tid = blockIdx.x * blockDim.x + threadIdx.x;
    int total = B * N * C4;
    if (tid >= total) return;
    int c4 = tid % C4;
    int n  = (tid / C4) % N;
    int b  = tid / (C4 * N);

    const float4* inb = (const float4*)in + (size_t)b * N * C4;
    int p0 = g_offs[n], p1 = g_offs[n + 1];
    int cnt = p1 - p0;
    float scale = 1.0f / (float)(cnt > 1 ? cnt : 1);

    float ax = 0.f, ay = 0.f, az = 0.f, aw = 0.f;
    int p = p0;
    for (; p + 4 <= p1; p += 4) {
        int   s0 = g_esrc[p],   s1 = g_esrc[p+1], s2 = g_esrc[p+2], s3 = g_esrc[p+3];
        float w0 = g_eew[p],    w1 = g_eew[p+1],  w2 = g_eew[p+2],  w3 = g_eew[p+3];
        float4 v0 = inb[(size_t)s0 * C4 + c4];
        float4 v1 = inb[(size_t)s1 * C4 + c4];
        float4 v2 = inb[(size_t)s2 * C4 + c4];
        float4 v3 = inb[(size_t)s3 * C4 + c4];
        ax += w0 * v0.x + w1 * v1.x + w2 * v2.x + w3 * v3.x;
        ay += w0 * v0.y + w1 * v1.y + w2 * v2.y + w3 * v3.y;
        az += w0 * v0.z + w1 * v1.z + w2 * v2.z + w3 * v3.z;
        aw += w0 * v0.w + w1 * v1.w + w2 * v2.w + w3 * v3.w;
    }
    for (; p < p1; p++) {
        int s = g_esrc[p];
        float w = g_eew[p];
        float4 v = inb[(size_t)s * C4 + c4];
        ax += w * v.x; ay += w * v.y; az += w * v.z; aw += w * v.w;
    }
    float4 r;
    r.x = ax * scale; r.y = ay * scale; r.z = az * scale; r.w = aw * scale;
    ((float4*)out)[(size_t)b * N * C4 + (size_t)n * C4 + c4] = r;
}

// ---------------- sage: emb = wmean(x)@Wr + x@Wroot + b ; xr = relu(emb) --------
// Block: 256 threads; 64 rows/block; each thread handles (row, 16 output cols)
__global__ void k_sage(const float* __restrict__ x,
                       const float* __restrict__ Wr, const float* __restrict__ Wroot,
                       const float* __restrict__ bias,
                       float* __restrict__ emb, int rows) {
    __shared__ float Wt[64 * 64];   // rows 0..31 = Wroot, rows 32..63 = Wr
    __shared__ float bs[64];
    int tx = threadIdx.x;
    for (int i = tx; i < 32 * 64; i += 256) {
        Wt[i]        = Wroot[i];
        Wt[2048 + i] = Wr[i];
    }
    if (tx < 64) bs[tx] = bias[tx];
    __syncthreads();

    int row = blockIdx.x * 64 + (tx >> 2);
    int j0  = (tx & 3) * 16;
    if (row >= rows) return;

    float xv[NF], av[NF];
    const float4* xp = (const float4*)(x      + (size_t)row * NF);
    const float4* ap = (const float4*)(g_aggx + (size_t)row * NF);
#pragma unroll
    for (int q = 0; q < 8; q++) {
        float4 v = xp[q];
        xv[q*4+0] = v.x; xv[q*4+1] = v.y; xv[q*4+2] = v.z; xv[q*4+3] = v.w;
        float4 u = ap[q];
        av[q*4+0] = u.x; av[q*4+1] = u.y; av[q*4+2] = u.z; av[q*4+3] = u.w;
    }
    float acc[16];
#pragma unroll
    for (int jj = 0; jj < 16; jj++) acc[jj] = bs[j0 + jj];
#pragma unroll
    for (int k = 0; k < 32; k++) {
        float xk = xv[k], ak = av[k];
        const float4* w0 = (const float4*)(Wt + k * 64 + j0);
        const float4* w1 = (const float4*)(Wt + 2048 + k * 64 + j0);
#pragma unroll
        for (int q = 0; q < 4; q++) {
            float4 a = w0[q], b4 = w1[q];
            acc[q*4+0] += xk * a.x + ak * b4.x;
            acc[q*4+1] += xk * a.y + ak * b4.y;
            acc[q*4+2] += xk * a.z + ak * b4.z;
            acc[q*4+3] += xk * a.w + ak * b4.w;
        }
    }
    float* ep  = emb  + (size_t)row * NH + j0;
    float* xrp = g_xr + (size_t)row * NH + j0;
#pragma unroll
    for (int jj = 0; jj < 16; jj++) {
        float v = acc[jj];
        ep[jj]  = v;
        xrp[jj] = fmaxf(v, 0.f);
    }
}

__global__ void k_zero_hc(int n) {
    int i = blockIdx.x * blockDim.x + threadIdx.x;
    if (i < n) { g_h[i] = 0.f; g_c[i] = 0.f; }
}

// ---------------- LSTM step: gates GEMM (8x8 register tiling) + cell update -----
// virtual K = 256: [0,64)=xr_t (Wroot rows 0..63), [64,128)=h (Wroot 64..127),
//                  [128,192)=axr_t (Wr 0..63), [192,256)=aggh (Wr 64..127)
// Block: 256 threads computes 64 nodes x 256 gate cols.
// Thread (ri = tx>>5, ci = tx&31) owns rows {ri, ri+8, ..., ri+56} x cols [8ci, 8ci+8).
__global__ void __launch_bounds__(256)
k_step(int t, const float* __restrict__ Wroot, const float* __restrict__ Wr,
       const float* __restrict__ bias, int h2slot, int N) {
    __shared__ float Ws[32 * 256];  // weight k-tile (reused for gate staging)
    __shared__ float Is[64 * 33];   // input tile, padded
    float acc[8][8];
    int tx = threadIdx.x;
    int ri = tx >> 5;       // 0..7
    int ci = tx & 31;       // 0..31
    int c0 = ci * 8;
    int n0 = blockIdx.x * 64;
    const float* xr_t  = g_xr  + (size_t)t * N * NH;
    const float* axr_t = g_axr + (size_t)t * N * NH;

#pragma unroll
    for (int q = 0; q < 8; q++)
#pragma unroll
        for (int j = 0; j < 8; j++) acc[q][j] = 0.f;

#pragma unroll 1
    for (int kt = 0; kt < 8; kt++) {
        int kvb = kt * 32;
        const float* Wm = (kvb < 128) ? (Wroot + (size_t)kvb * NG)
                                      : (Wr + (size_t)(kvb - 128) * NG);
        // copy 32x256 weight tile (contiguous, float4)
        {
            const float4* s4 = (const float4*)Wm;
            float4* d4 = (float4*)Ws;
#pragma unroll
            for (int j = 0; j < 8; j++) d4[tx + 256 * j] = s4[tx + 256 * j];
        }
        const float* srcp; int coff;
        if (kvb < 64)       { srcp = xr_t;   coff = kvb;       }
        else if (kvb < 128) { srcp = g_h;    coff = kvb - 64;  }
        else if (kvb < 192) { srcp = axr_t;  coff = kvb - 128; }
        else                { srcp = g_aggh; coff = kvb - 192; }
        // load 64 rows x 32 k (coalesced gmem, conflict-free smem store)
#pragma unroll
        for (int j = 0; j < 8; j++) {
            int id = tx + 256 * j;
            int r = id >> 5, k = id & 31;
            int n = n0 + r;
            Is[r * 33 + k] = (n < N) ? srcp[(size_t)n * NH + coff + k] : 0.f;
        }
        __syncthreads();
#pragma unroll
        for (int k = 0; k < 32; k++) {
            const float4* wp = (const float4*)(Ws + k * 256 + c0);
            float4 w0 = wp[0], w1 = wp[1];
#pragma unroll
            for (int q = 0; q < 8; q++) {
                float a = Is[(ri + 8 * q) * 33 + k];
                acc[q][0] += a * w0.x; acc[q][1] += a * w0.y;
                acc[q][2] += a * w0.z; acc[q][3] += a * w0.w;
                acc[q][4] += a * w1.x; acc[q][5] += a * w1.y;
                acc[q][6] += a * w1.z; acc[q][7] += a * w1.w;
            }
        }
        __syncthreads();
    }

    float breg[8];
#pragma unroll
    for (int j = 0; j < 8; j++) breg[j] = bias[c0 + j];

    // stage gates + fused cell update, 32 rows per phase (reuse Ws as staging)
#pragma unroll 1
    for (int ph = 0; ph < 2; ph++) {
#pragma unroll
        for (int q = 0; q < 4; q++) {
            int qq = ph * 4 + q;
            int rl = ri + 8 * qq - ph * 32;   // 0..31 within phase
            float4 v0, v1;
            v0.x = acc[qq][0] + breg[0]; v0.y = acc[qq][1] + breg[1];
            v0.z = acc[qq][2] + breg[2]; v0.w = acc[qq][3] + breg[3];
            v1.x = acc[qq][4] + breg[4]; v1.y = acc[qq][5] + breg[5];
            v1.z = acc[qq][6] + breg[6]; v1.w = acc[qq][7] + breg[7];
            float4* dst = (float4*)(Ws + rl * 256 + c0);
            dst[0] = v0; dst[1] = v1;
        }
        __syncthreads();
        for (int i = tx; i < 32 * 64; i += 256) {
            int rl = i >> 6, hc = i & 63;
            int n = n0 + ph * 32 + rl;
            if (n < N) {
                float ig = Ws[rl * 256 + hc];
                float fg = Ws[rl * 256 + 64  + hc];
                float gg = Ws[rl * 256 + 128 + hc];
                float og = Ws[rl * 256 + 192 + hc];
                float si = 1.f / (1.f + __expf(-ig));
                float sf = 1.f / (1.f + __expf(-fg));
                float so = 1.f / (1.f + __expf(-og));
                float tg = tanhf(gg);
                size_t idx = (size_t)n * NH + hc;
                float cn = sf * g_c[idx] + si * tg;
                float hn = so * tanhf(cn);
                g_c[idx] = cn;
                g_h[idx] = hn;
                if (h2slot >= 0) g_h2[((size_t)h2slot * N + n) * NH + hc] = hn;
            }
        }
        __syncthreads();
    }
}

// ---------------- output head: out = concat(xr[8..11], h2) @ W_out + b_out -------
__global__ void k_out(const float* __restrict__ Wout, const float* __restrict__ bout,
                      float* __restrict__ out, int N) {
    __shared__ float Ws[128 * 8];
    __shared__ float bs[8];
    int tx = threadIdx.x;
    for (int i = tx; i < 1024; i += 256) Ws[i] = Wout[i];
    if (tx < 8) bs[tx] = bout[tx];
    __syncthreads();
    int tid = blockIdx.x * 256 + tx;
    if (tid >= 4 * N) return;
    int tp = tid / N, n = tid % N;
    float acc[8];
#pragma unroll
    for (int o = 0; o < 8; o++) acc[o] = bs[o];
    const float4* xrow = (const float4*)(g_xr + ((size_t)(8 + tp) * N + n) * NH);
    const float4* hrow = (const float4*)(g_h2 + ((size_t)tp * N + n) * NH);
#pragma unroll
    for (int q = 0; q < 16; q++) {
        float4 v = xrow[q];
        int k = q * 4;
#pragma unroll
        for (int o = 0; o < 8; o++) {
            acc[o] += v.x * Ws[(k+0)*8+o] + v.y * Ws[(k+1)*8+o]
                    + v.z * Ws[(k+2)*8+o] + v.w * Ws[(k+3)*8+o];
        }
    }
#pragma unroll
    for (int q = 0; q < 16; q++) {
        float4 v = hrow[q];
        int k = 64 + q * 4;
#pragma unroll
        for (int o = 0; o < 8; o++) {
            acc[o] += v.x * Ws[(k+0)*8+o] + v.y * Ws[(k+1)*8+o]
                    + v.z * Ws[(k+2)*8+o] + v.w * Ws[(k+3)*8+o];
        }
    }
#pragma unroll
    for (int o = 0; o < 8; o++) out[(size_t)tid * 8 + o] = acc[o];
}

__global__ void k_copy_c2(float* __restrict__ dst, int n) {
    int i = blockIdx.x * blockDim.x + threadIdx.x;
    if (i < n) dst[i] = g_c[i];
}

// ---------------- launch ----------------
extern "C" void kernel_launch(void* const* d_in, const int* in_sizes, int n_in,
                              void* d_out, int out_size) {
    const float* x       = (const float*)d_in[0];
    const int*   eidx    = (const int*)  d_in[1];
    const float* ew      = (const float*)d_in[2];
    const float* sWr     = (const float*)d_in[3];
    const float* sWroot  = (const float*)d_in[4];
    const float* sb      = (const float*)d_in[5];
    const float* l1Wr    = (const float*)d_in[6];
    const float* l1Wroot = (const float*)d_in[7];
    const float* l1b     = (const float*)d_in[8];
    const float* l2Wr    = (const float*)d_in[9];
    const float* l2Wroot = (const float*)d_in[10];
    const float* l2b     = (const float*)d_in[11];
    const float* Wout    = (const float*)d_in[12];
    const float* bout    = (const float*)d_in[13];

    int E = in_sizes[2];
    int N = in_sizes[0] / (TT * NF);
    const int* srcv = eidx;
    const int* dstv = eidx + E;

    // output layout: [out (4*N*8) | c2 (N*64) | emb (T*N*64)]
    float* out_out = (float*)d_out;
    float* out_c2  = out_out + (size_t)4 * N * NO;
    float* out_emb = out_c2  + (size_t)N * NH;

    // CSR build
    k_zero_cnt<<<(N + 255) / 256, 256>>>(N);
    k_count<<<(E + 255) / 256, 256>>>(dstv, E);
    k_scan<<<1, 1024>>>(N);
    k_scatter<<<(E + 255) / 256, 256>>>(srcv, dstv, ew, E);

    // sage: aggregate x (all T), then emb/xr
    int aggx_threads = TT * N * (NF / 4);
    k_aggregate<<<(aggx_threads + 255) / 256, 256>>>(x, 0, N, NF / 4, TT);
    k_sage<<<(TT * N + 63) / 64, 256>>>(x, sWr, sWroot, sb, out_emb, TT * N);

    // axr = wmean(xr) for all T (shared by both LSTMs, all steps)
    int axr_threads = TT * N * (NH / 4);
    k_aggregate<<<(axr_threads + 255) / 256, 256>>>(nullptr, 1, N, NH / 4, TT);

    k_zero_hc<<<(N * NH + 255) / 256, 256>>>(N * NH);

    // 24 sequential LSTM steps (lstm1 s=0..11, lstm2 s=12..23; h,c carry over)
    int ha_threads = N * (NH / 4);
    for (int s = 0; s < 24; s++) {
        int t = s % TT;
        const float* Wr    = (s < 12) ? l1Wr    : l2Wr;
        const float* Wroot = (s < 12) ? l1Wroot : l2Wroot;
        const float* bb    = (s < 12) ? l1b     : l2b;
        k_aggregate<<<(ha_threads + 255) / 256, 256>>>(nullptr, 2, N, NH / 4, 1);
        int h2slot = (s >= 20) ? (s - 20) : -1;
        k_step<<<(N + 63) / 64, 256>>>(t, Wroot, Wr, bb, h2slot, N);
    }

    k_out<<<(4 * N + 255) / 256, 256>>>(Wout, bout, out_out, N);
    k_copy_c2<<<(N * NH + 255) / 256, 256>>>(out_c2, N * NH);
}

// round 9
// speedup vs baseline: 1.7983x; 1.7983x over previous
#include <cuda_runtime.h>
#include <math.h>
#include <stdint.h>

// Problem constants (fixed by setup_inputs)
#define TT   12
#define NF   32
#define NH   64
#define NG   256   // 4H
#define NO   8
#define MAXN 20000
#define MAXE 400000

// ---------------- device scratch (static, no allocation) ----------------
__device__ int   g_cnt [MAXN];
__device__ int   g_offs[MAXN + 1];
__device__ int   g_cur [MAXN];
__device__ int   g_esrc[MAXE];
__device__ float g_eew [MAXE];
__device__ float g_aggx[(size_t)TT * MAXN * NF];  // normalized wmean(x)  [T,N,F]
__device__ float g_xr  [(size_t)TT * MAXN * NH];  // relu(emb)            [T,N,H]
__device__ float g_axr [(size_t)TT * MAXN * NH];  // normalized wmean(xr) [T,N,H]
__device__ float g_aggh[(size_t)MAXN * NH];       // normalized wmean(h)  [N,H]
__device__ float g_h   [(size_t)MAXN * NH];
__device__ float g_c   [(size_t)MAXN * NH];
__device__ float g_h2  [(size_t)4 * MAXN * NH];   // h2 at t=8..11

// ---------------- CSR build ----------------
__global__ void k_zero_cnt(int N) {
    int i = blockIdx.x * blockDim.x + threadIdx.x;
    if (i < N) g_cnt[i] = 0;
}

__global__ void k_count(const int* __restrict__ dstv, int E) {
    int e = blockIdx.x * blockDim.x + threadIdx.x;
    if (e < E) atomicAdd(&g_cnt[dstv[e]], 1);
}

// single-block exclusive scan over counts -> offsets (+ cursor copy)
__global__ void k_scan(int N) {
    __shared__ int sh[1024];
    int tx = threadIdx.x;
    int total = 0;
    for (int base = 0; base < N; base += 1024) {
        int i = base + tx;
        int v = (i < N) ? g_cnt[i] : 0;
        sh[tx] = v;
        __syncthreads();
        for (int d = 1; d < 1024; d <<= 1) {
            int t = (tx >= d) ? sh[tx - d] : 0;
            __syncthreads();
            sh[tx] += t;
            __syncthreads();
        }
        if (i < N) {
            int ex = total + sh[tx] - v;
            g_offs[i] = ex;
            g_cur[i]  = ex;
        }
        total += sh[1023];
        __syncthreads();
    }
    if (tx == 0) g_offs[N] = total;
}

__global__ void k_scatter(const int* __restrict__ srcv, const int* __restrict__ dstv,
                          const float* __restrict__ ew, int E) {
    int e = blockIdx.x * blockDim.x + threadIdx.x;
    if (e >= E) return;
    int d = dstv[e];
    int p = atomicAdd(&g_cur[d], 1);
    g_esrc[p] = srcv[e];
    g_eew[p]  = ew[e];
}

// ---------------- generic gather aggregation (normalized) ----------------
__global__ void k_aggregate(const float* __restrict__ in_ext, int mode, int N, int C4, int B) {
    const float* in;
    float* out;
    if (mode == 0)      { in = in_ext; out = g_aggx; }
    else if (mode == 1) { in = g_xr;   out = g_axr;  }
    else                { in = g_h;    out = g_aggh; }

    int tid = blockIdx.x * blockDim.x + threadIdx.x;
    int total = B * N * C4;
    if (tid >= total) return;
    int c4 = tid % C4;
    int n  = (tid / C4) % N;
    int b  = tid / (C4 * N);

    const float4* inb = (const float4*)in + (size_t)b * N * C4;
    int p0 = g_offs[n], p1 = g_offs[n + 1];
    int cnt = p1 - p0;
    float scale = 1.0f / (float)(cnt > 1 ? cnt : 1);

    float ax = 0.f, ay = 0.f, az = 0.f, aw = 0.f;
    int p = p0;
    for (; p + 4 <= p1; p += 4) {
        int   s0 = g_esrc[p],   s1 = g_esrc[p+1], s2 = g_esrc[p+2], s3 = g_esrc[p+3];
        float w0 = g_eew[p],    w1 = g_eew[p+1],  w2 = g_eew[p+2],  w3 = g_eew[p+3];
        float4 v0 = inb[(size_t)s0 * C4 + c4];
        float4 v1 = inb[(size_t)s1 * C4 + c4];
        float4 v2 = inb[(size_t)s2 * C4 + c4];
        float4 v3 = inb[(size_t)s3 * C4 + c4];
        ax += w0 * v0.x + w1 * v1.x + w2 * v2.x + w3 * v3.x;
        ay += w0 * v0.y + w1 * v1.y + w2 * v2.y + w3 * v3.y;
        az += w0 * v0.z + w1 * v1.z + w2 * v2.z + w3 * v3.z;
        aw += w0 * v0.w + w1 * v1.w + w2 * v2.w + w3 * v3.w;
    }
    for (; p < p1; p++) {
        int s = g_esrc[p];
        float w = g_eew[p];
        float4 v = inb[(size_t)s * C4 + c4];
        ax += w * v.x; ay += w * v.y; az += w * v.z; aw += w * v.w;
    }
    float4 r;
    r.x = ax * scale; r.y = ay * scale; r.z = az * scale; r.w = aw * scale;
    ((float4*)out)[(size_t)b * N * C4 + (size_t)n * C4 + c4] = r;
}

// ---------------- sage: emb = wmean(x)@Wr + x@Wroot + b ; xr = relu(emb) --------
__global__ void k_sage(const float* __restrict__ x,
                       const float* __restrict__ Wr, const float* __restrict__ Wroot,
                       const float* __restrict__ bias,
                       float* __restrict__ emb, int rows) {
    __shared__ float Wt[64 * 64];
    __shared__ float bs[64];
    int tx = threadIdx.x;
    for (int i = tx; i < 32 * 64; i += 256) {
        Wt[i]        = Wroot[i];
        Wt[2048 + i] = Wr[i];
    }
    if (tx < 64) bs[tx] = bias[tx];
    __syncthreads();

    int row = blockIdx.x * 64 + (tx >> 2);
    int j0  = (tx & 3) * 16;
    if (row >= rows) return;

    float xv[NF], av[NF];
    const float4* xp = (const float4*)(x      + (size_t)row * NF);
    const float4* ap = (const float4*)(g_aggx + (size_t)row * NF);
#pragma unroll
    for (int q = 0; q < 8; q++) {
        float4 v = xp[q];
        xv[q*4+0] = v.x; xv[q*4+1] = v.y; xv[q*4+2] = v.z; xv[q*4+3] = v.w;
        float4 u = ap[q];
        av[q*4+0] = u.x; av[q*4+1] = u.y; av[q*4+2] = u.z; av[q*4+3] = u.w;
    }
    float acc[16];
#pragma unroll
    for (int jj = 0; jj < 16; jj++) acc[jj] = bs[j0 + jj];
#pragma unroll
    for (int k = 0; k < 32; k++) {
        float xk = xv[k], ak = av[k];
        const float4* w0 = (const float4*)(Wt + k * 64 + j0);
        const float4* w1 = (const float4*)(Wt + 2048 + k * 64 + j0);
#pragma unroll
        for (int q = 0; q < 4; q++) {
            float4 a = w0[q], b4 = w1[q];
            acc[q*4+0] += xk * a.x + ak * b4.x;
            acc[q*4+1] += xk * a.y + ak * b4.y;
            acc[q*4+2] += xk * a.z + ak * b4.z;
            acc[q*4+3] += xk * a.w + ak * b4.w;
        }
    }
    float* ep  = emb  + (size_t)row * NH + j0;
    float* xrp = g_xr + (size_t)row * NH + j0;
#pragma unroll
    for (int jj = 0; jj < 16; jj++) {
        float v = acc[jj];
        ep[jj]  = v;
        xrp[jj] = fmaxf(v, 0.f);
    }
}

__global__ void k_zero_hc(int n) {
    int i = blockIdx.x * blockDim.x + threadIdx.x;
    if (i < n) { g_h[i] = 0.f; g_c[i] = 0.f; }
}

// ---------------- tf32 helpers ----------------
__device__ __forceinline__ float f2tf(float x) {
    uint32_t u;
    asm("cvt.rna.tf32.f32 %0, %1;" : "=r"(u) : "f"(x));
    return __uint_as_float(u);
}

__device__ __forceinline__ void mma_tf32(float* c, const uint32_t* a, uint32_t b0, uint32_t b1) {
    asm volatile(
        "mma.sync.aligned.m16n8k8.row.col.f32.tf32.tf32.f32 "
        "{%0,%1,%2,%3}, {%4,%5,%6,%7}, {%8,%9}, {%0,%1,%2,%3};\n"
        : "+f"(c[0]), "+f"(c[1]), "+f"(c[2]), "+f"(c[3])
        : "r"(a[0]), "r"(a[1]), "r"(a[2]), "r"(a[3]), "r"(b0), "r"(b1));
}

// ---------------- LSTM step: gates GEMM (tf32 mma.sync) + fused cell update -----
// virtual K = 256: [0,64)=xr_t (Wroot 0..63), [64,128)=h (Wroot 64..127),
//                  [128,192)=axr_t (Wr 0..63), [192,256)=aggh (Wr 64..127)
// Block: 256 threads (8 warps) -> 64 nodes x 256 gate cols.
// Warp w: row group rg=w>>2 (rows 32rg..+32), col group cg=w&3 (cols 64cg..+64).
// Per warp: 2 m16 tiles x 8 n8 tiles of m16n8k8 tf32 mma.
#define WS_LD 264   // Ws row stride (floats): banks 8t+g bijective, 16B aligned
#define IS_LD 36    // Is row stride: banks 4g+t bijective, 16B aligned
__global__ void __launch_bounds__(256)
k_step(int t, const float* __restrict__ Wroot, const float* __restrict__ Wr,
       const float* __restrict__ bias, int h2slot, int N) {
    __shared__ float Ws[32 * WS_LD];  // tf32 weight k-tile; reused for gate staging
    __shared__ float Is[64 * IS_LD];  // tf32 input tile
    __shared__ float bs[NG];

    int tx   = threadIdx.x;
    int wid  = tx >> 5;
    int lane = tx & 31;
    int g    = lane >> 2;    // 0..7
    int tq   = lane & 3;     // 0..3
    int rg   = wid >> 2;     // 0..1
    int cg   = wid & 3;      // 0..3
    int n0   = blockIdx.x * 64;

    const float* xr_t  = g_xr  + (size_t)t * N * NH;
    const float* axr_t = g_axr + (size_t)t * N * NH;

    bs[tx] = bias[tx];

    float acc[2][8][4];
#pragma unroll
    for (int mt = 0; mt < 2; mt++)
#pragma unroll
        for (int nt = 0; nt < 8; nt++)
#pragma unroll
            for (int q = 0; q < 4; q++) acc[mt][nt][q] = 0.f;

#pragma unroll 1
    for (int kt = 0; kt < 8; kt++) {
        int kvb = kt * 32;
        const float* Wm = (kvb < 128) ? (Wroot + (size_t)kvb * NG)
                                      : (Wr + (size_t)(kvb - 128) * NG);
        // stage 32x256 weight tile, tf32-rounded (float4 in/out)
        {
            const float4* s4 = (const float4*)Wm;
#pragma unroll
            for (int j = 0; j < 8; j++) {
                int id = tx + 256 * j;          // float4 index
                int row = id >> 6, c4 = id & 63;
                float4 v = s4[id];
                v.x = f2tf(v.x); v.y = f2tf(v.y); v.z = f2tf(v.z); v.w = f2tf(v.w);
                *(float4*)(Ws + row * WS_LD + c4 * 4) = v;
            }
        }
        const float* srcp; int coff;
        if (kvb < 64)       { srcp = xr_t;   coff = kvb;       }
        else if (kvb < 128) { srcp = g_h;    coff = kvb - 64;  }
        else if (kvb < 192) { srcp = axr_t;  coff = kvb - 128; }
        else                { srcp = g_aggh; coff = kvb - 192; }
        // stage 64 rows x 32 k input tile, tf32-rounded
#pragma unroll
        for (int j = 0; j < 8; j++) {
            int id = tx + 256 * j;
            int r = id >> 5, k = id & 31;
            int n = n0 + r;
            Is[r * IS_LD + k] = (n < N) ? f2tf(srcp[(size_t)n * NH + coff + k]) : 0.f;
        }
        __syncthreads();

#pragma unroll
        for (int k8 = 0; k8 < 4; k8++) {
            int k0 = k8 * 8;
            uint32_t afr[2][4];
#pragma unroll
            for (int mt = 0; mt < 2; mt++) {
                int br = rg * 32 + mt * 16 + g;
                afr[mt][0] = __float_as_uint(Is[(br)     * IS_LD + k0 + tq]);
                afr[mt][1] = __float_as_uint(Is[(br + 8) * IS_LD + k0 + tq]);
                afr[mt][2] = __float_as_uint(Is[(br)     * IS_LD + k0 + tq + 4]);
                afr[mt][3] = __float_as_uint(Is[(br + 8) * IS_LD + k0 + tq + 4]);
            }
#pragma unroll
            for (int nt = 0; nt < 8; nt++) {
                int n = cg * 64 + nt * 8 + g;
                uint32_t b0 = __float_as_uint(Ws[(k0 + tq)     * WS_LD + n]);
                uint32_t b1 = __float_as_uint(Ws[(k0 + tq + 4) * WS_LD + n]);
                mma_tf32(acc[0][nt], afr[0], b0, b1);
                mma_tf32(acc[1][nt], afr[1], b0, b1);
            }
        }
        __syncthreads();
    }

    // epilogue: stage gates (reuse Ws) + fused cell update, 32 rows per phase
#pragma unroll 1
    for (int ph = 0; ph < 2; ph++) {
        if (rg == ph) {
#pragma unroll
            for (int mt = 0; mt < 2; mt++) {
#pragma unroll
                for (int nt = 0; nt < 8; nt++) {
                    int col = cg * 64 + nt * 8 + 2 * tq;
                    int r0 = mt * 16 + g;
                    Ws[(r0)     * WS_LD + col]     = acc[mt][nt][0];
                    Ws[(r0)     * WS_LD + col + 1] = acc[mt][nt][1];
                    Ws[(r0 + 8) * WS_LD + col]     = acc[mt][nt][2];
                    Ws[(r0 + 8) * WS_LD + col + 1] = acc[mt][nt][3];
                }
            }
        }
        __syncthreads();
        for (int i = tx; i < 32 * 64; i += 256) {
            int rl = i >> 6, hc = i & 63;
            int n = n0 + ph * 32 + rl;
            if (n < N) {
                float ig = Ws[rl * WS_LD + hc]       + bs[hc];
                float fg = Ws[rl * WS_LD + 64  + hc] + bs[64 + hc];
                float gg = Ws[rl * WS_LD + 128 + hc] + bs[128 + hc];
                float og = Ws[rl * WS_LD + 192 + hc] + bs[192 + hc];
                float si = 1.f / (1.f + __expf(-ig));
                float sf = 1.f / (1.f + __expf(-fg));
                float so = 1.f / (1.f + __expf(-og));
                float tg = tanhf(gg);
                size_t idx = (size_t)n * NH + hc;
                float cn = sf * g_c[idx] + si * tg;
                float hn = so * tanhf(cn);
                g_c[idx] = cn;
                g_h[idx] = hn;
                if (h2slot >= 0) g_h2[((size_t)h2slot * N + n) * NH + hc] = hn;
            }
        }
        __syncthreads();
    }
}

// ---------------- output head: out = concat(xr[8..11], h2) @ W_out + b_out -------
__global__ void k_out(const float* __restrict__ Wout, const float* __restrict__ bout,
                      float* __restrict__ out, int N) {
    __shared__ float Ws[128 * 8];
    __shared__ float bs[8];
    int tx = threadIdx.x;
    for (int i = tx; i < 1024; i += 256) Ws[i] = Wout[i];
    if (tx < 8) bs[tx] = bout[tx];
    __syncthreads();
    int tid = blockIdx.x * 256 + tx;
    if (tid >= 4 * N) return;
    int tp = tid / N, n = tid % N;
    float acc[8];
#pragma unroll
    for (int o = 0; o < 8; o++) acc[o] = bs[o];
    const float4* xrow = (const float4*)(g_xr + ((size_t)(8 + tp) * N + n) * NH);
    const float4* hrow = (const float4*)(g_h2 + ((size_t)tp * N + n) * NH);
#pragma unroll
    for (int q = 0; q < 16; q++) {
        float4 v = xrow[q];
        int k = q * 4;
#pragma unroll
        for (int o = 0; o < 8; o++) {
            acc[o] += v.x * Ws[(k+0)*8+o] + v.y * Ws[(k+1)*8+o]
                    + v.z * Ws[(k+2)*8+o] + v.w * Ws[(k+3)*8+o];
        }
    }
#pragma unroll
    for (int q = 0; q < 16; q++) {
        float4 v = hrow[q];
        int k = 64 + q * 4;
#pragma unroll
        for (int o = 0; o < 8; o++) {
            acc[o] += v.x * Ws[(k+0)*8+o] + v.y * Ws[(k+1)*8+o]
                    + v.z * Ws[(k+2)*8+o] + v.w * Ws[(k+3)*8+o];
        }
    }
#pragma unroll
    for (int o = 0; o < 8; o++) out[(size_t)tid * 8 + o] = acc[o];
}

__global__ void k_copy_c2(float* __restrict__ dst, int n) {
    int i = blockIdx.x * blockDim.x + threadIdx.x;
    if (i < n) dst[i] = g_c[i];
}

// ---------------- launch ----------------
extern "C" void kernel_launch(void* const* d_in, const int* in_sizes, int n_in,
                              void* d_out, int out_size) {
    const float* x       = (const float*)d_in[0];
    const int*   eidx    = (const int*)  d_in[1];
    const float* ew      = (const float*)d_in[2];
    const float* sWr     = (const float*)d_in[3];
    const float* sWroot  = (const float*)d_in[4];
    const float* sb      = (const float*)d_in[5];
    const float* l1Wr    = (const float*)d_in[6];
    const float* l1Wroot = (const float*)d_in[7];
    const float* l1b     = (const float*)d_in[8];
    const float* l2Wr    = (const float*)d_in[9];
    const float* l2Wroot = (const float*)d_in[10];
    const float* l2b     = (const float*)d_in[11];
    const float* Wout    = (const float*)d_in[12];
    const float* bout    = (const float*)d_in[13];

    int E = in_sizes[2];
    int N = in_sizes[0] / (TT * NF);
    const int* srcv = eidx;
    const int* dstv = eidx + E;

    // output layout: [out (4*N*8) | c2 (N*64) | emb (T*N*64)]
    float* out_out = (float*)d_out;
    float* out_c2  = out_out + (size_t)4 * N * NO;
    float* out_emb = out_c2  + (size_t)N * NH;

    // CSR build
    k_zero_cnt<<<(N + 255) / 256, 256>>>(N);
    k_count<<<(E + 255) / 256, 256>>>(dstv, E);
    k_scan<<<1, 1024>>>(N);
    k_scatter<<<(E + 255) / 256, 256>>>(srcv, dstv, ew, E);

    // sage: aggregate x (all T), then emb/xr
    int aggx_threads = TT * N * (NF / 4);
    k_aggregate<<<(aggx_threads + 255) / 256, 256>>>(x, 0, N, NF / 4, TT);
    k_sage<<<(TT * N + 63) / 64, 256>>>(x, sWr, sWroot, sb, out_emb, TT * N);

    // axr = wmean(xr) for all T (shared by both LSTMs, all steps)
    int axr_threads = TT * N * (NH / 4);
    k_aggregate<<<(axr_threads + 255) / 256, 256>>>(nullptr, 1, N, NH / 4, TT);

    k_zero_hc<<<(N * NH + 255) / 256, 256>>>(N * NH);

    // 24 sequential LSTM steps (lstm1 s=0..11, lstm2 s=12..23; h,c carry over)
    int ha_threads = N * (NH / 4);
    for (int s = 0; s < 24; s++) {
        int t = s % TT;
        const float* Wr    = (s < 12) ? l1Wr    : l2Wr;
        const float* Wroot = (s < 12) ? l1Wroot : l2Wroot;
        const float* bb    = (s < 12) ? l1b     : l2b;
        k_aggregate<<<(ha_threads + 255) / 256, 256>>>(nullptr, 2, N, NH / 4, 1);
        int h2slot = (s >= 20) ? (s - 20) : -1;
        k_step<<<(N + 63) / 64, 256>>>(t, Wroot, Wr, bb, h2slot, N);
    }

    k_out<<<(4 * N + 255) / 256, 256>>>(Wout, bout, out_out, N);
    k_copy_c2<<<(N * NH + 255) / 256, 256>>>(out_c2, N * NH);
}